// round 1
// baseline (speedup 1.0000x reference)
#include <cuda_runtime.h>
#include <cuda_bf16.h>
#include <math.h>

#define NN 50000
#define EE 100000
#define HH 768
#define NHD 12
#define HDD 64
#define NGR 64
#define NCL 10
#define H2 384

// ---------------- scratch (static device globals; no allocation) ----------------
__device__ float g_bufA[(size_t)NN * HH];
__device__ float g_bufB[(size_t)NN * HH];
__device__ float g_bufC[(size_t)NN * HH];
__device__ float g_dinv[NN];
__device__ int   g_cnt[NN];
__device__ int   g_rowstart[NN + 1];
__device__ int   g_cursor[NN];
__device__ int   g_csrsrc[EE];
__device__ float g_as[NN * NHD];
__device__ float g_ad[NN * NHD];
__device__ float g_pool[NGR * HH];
__device__ float g_zmlp[NGR * H2];

__device__ __forceinline__ float lrelu(float x) { return x > 0.f ? x : 0.2f * x; }

// ---------------- CSR build ----------------
__global__ void k_zero_cnt() {
    int i = blockIdx.x * blockDim.x + threadIdx.x;
    if (i < NN) g_cnt[i] = 0;
}

__global__ void k_count(const int* __restrict__ ei) {
    int e = blockIdx.x * blockDim.x + threadIdx.x;
    if (e < EE) atomicAdd(&g_cnt[ei[EE + e]], 1);
}

__global__ void k_scan() {
    __shared__ int sh[1024];
    int tid = threadIdx.x;
    int off = 0;
    for (int base = 0; base < NN; base += 1024) {
        int i = base + tid;
        int v = (i < NN) ? g_cnt[i] : 0;
        sh[tid] = v;
        __syncthreads();
        for (int s = 1; s < 1024; s <<= 1) {
            int t = (tid >= s) ? sh[tid - s] : 0;
            __syncthreads();
            sh[tid] += t;
            __syncthreads();
        }
        if (i < NN) {
            int excl = off + sh[tid] - v;
            g_rowstart[i] = excl;
            g_cursor[i] = excl;
        }
        int tot = sh[1023];
        __syncthreads();
        off += tot;
    }
    if (tid == 0) g_rowstart[NN] = off;
}

__global__ void k_dinv() {
    int i = blockIdx.x * blockDim.x + threadIdx.x;
    if (i < NN) g_dinv[i] = rsqrtf((float)(g_cnt[i] + 1));
}

__global__ void k_fill(const int* __restrict__ ei) {
    int e = blockIdx.x * blockDim.x + threadIdx.x;
    if (e < EE) {
        int s = ei[e];
        int d = ei[EE + e];
        int pos = atomicAdd(&g_cursor[d], 1);
        g_csrsrc[pos] = s;
    }
}

// ---------------- first-layer linear (K = 3) ----------------
__global__ void k_lin3(const float* __restrict__ x, const float* __restrict__ w,
                       float* __restrict__ T) {
    int n = blockIdx.x;
    float x0 = x[n * 3 + 0], x1 = x[n * 3 + 1], x2 = x[n * 3 + 2];
    for (int f = threadIdx.x; f < HH; f += 256) {
        T[(size_t)n * HH + f] = x0 * w[f] + x1 * w[HH + f] + x2 * w[2 * HH + f];
    }
}

// ---------------- SGEMM: C[M,768] = A[M,768] @ B[768,768] ----------------
#define BM 128
#define BN 128
#define BK 16
__global__ __launch_bounds__(256) void k_sgemm(const float* __restrict__ A,
                                               const float* __restrict__ B,
                                               float* __restrict__ C, int M) {
    __shared__ float As[BK][BM];
    __shared__ float Bs[BK][BN];
    int row0 = blockIdx.x * BM;
    int col0 = blockIdx.y * BN;
    int tid = threadIdx.x;
    int tx = tid & 15, ty = tid >> 4;

    float acc[8][8];
#pragma unroll
    for (int i = 0; i < 8; i++)
#pragma unroll
        for (int j = 0; j < 8; j++) acc[i][j] = 0.f;

    int arow = tid >> 2;
    int acol = (tid & 3) * 4;
    int brow = tid >> 5;
    int bcol = (tid & 31) * 4;

    for (int k0 = 0; k0 < HH; k0 += BK) {
#pragma unroll
        for (int r = 0; r < 2; r++) {
            int gr = row0 + arow + r * 64;
            float4 v = make_float4(0.f, 0.f, 0.f, 0.f);
            if (gr < M) v = *(const float4*)&A[(size_t)gr * HH + k0 + acol];
            As[acol + 0][arow + r * 64] = v.x;
            As[acol + 1][arow + r * 64] = v.y;
            As[acol + 2][arow + r * 64] = v.z;
            As[acol + 3][arow + r * 64] = v.w;
        }
#pragma unroll
        for (int r = 0; r < 2; r++) {
            int gk = k0 + brow + r * 8;
            *(float4*)&Bs[brow + r * 8][bcol] =
                *(const float4*)&B[(size_t)gk * HH + col0 + bcol];
        }
        __syncthreads();
#pragma unroll
        for (int kk = 0; kk < BK; kk++) {
            float a[8], b[8];
            *(float4*)&a[0] = *(const float4*)&As[kk][ty * 8];
            *(float4*)&a[4] = *(const float4*)&As[kk][ty * 8 + 4];
            *(float4*)&b[0] = *(const float4*)&Bs[kk][tx * 8];
            *(float4*)&b[4] = *(const float4*)&Bs[kk][tx * 8 + 4];
#pragma unroll
            for (int i = 0; i < 8; i++)
#pragma unroll
                for (int j = 0; j < 8; j++) acc[i][j] += a[i] * b[j];
        }
        __syncthreads();
    }

#pragma unroll
    for (int i = 0; i < 8; i++) {
        int gr = row0 + ty * 8 + i;
        if (gr < M) {
            float4 v0 = make_float4(acc[i][0], acc[i][1], acc[i][2], acc[i][3]);
            float4 v1 = make_float4(acc[i][4], acc[i][5], acc[i][6], acc[i][7]);
            *(float4*)&C[(size_t)gr * HH + col0 + tx * 8] = v0;
            *(float4*)&C[(size_t)gr * HH + col0 + tx * 8 + 4] = v1;
        }
    }
}

// ---------------- GCN aggregation (+bias+relu) ----------------
__global__ __launch_bounds__(256) void k_gcn_agg(const float* __restrict__ T,
                                                 float* __restrict__ out,
                                                 const float* __restrict__ bias) {
    int n = blockIdx.x;
    float din = g_dinv[n];
    int s0 = g_rowstart[n], s1 = g_rowstart[n + 1];
    int f = threadIdx.x;
    float selfw = din * din;
    const float* rn = T + (size_t)n * HH;
    float a0 = rn[f] * selfw;
    float a1 = rn[f + 256] * selfw;
    float a2 = rn[f + 512] * selfw;
    for (int j = s0; j < s1; j++) {
        int s = g_csrsrc[j];
        float w = g_dinv[s] * din;
        const float* row = T + (size_t)s * HH;
        a0 += row[f] * w;
        a1 += row[f + 256] * w;
        a2 += row[f + 512] * w;
    }
    a0 += bias[f]; a1 += bias[f + 256]; a2 += bias[f + 512];
    float* o = out + (size_t)n * HH;
    o[f] = fmaxf(a0, 0.f);
    o[f + 256] = fmaxf(a1, 0.f);
    o[f + 512] = fmaxf(a2, 0.f);
}

// ---------------- GAT alpha (per node, per head dot products) ----------------
__global__ void k_alpha(const float* __restrict__ Hg, const float* __restrict__ a_src,
                        const float* __restrict__ a_dst) {
    int gwarp = (blockIdx.x * blockDim.x + threadIdx.x) >> 5;
    int lane = threadIdx.x & 31;
    if (gwarp >= NN * NHD) return;
    int n = gwarp / NHD, h = gwarp % NHD;
    const float* row = Hg + (size_t)n * HH + h * HDD;
    float v0 = row[lane], v1 = row[lane + 32];
    float s = v0 * a_src[h * HDD + lane] + v1 * a_src[h * HDD + lane + 32];
    float d = v0 * a_dst[h * HDD + lane] + v1 * a_dst[h * HDD + lane + 32];
#pragma unroll
    for (int o = 16; o; o >>= 1) {
        s += __shfl_xor_sync(0xFFFFFFFFu, s, o);
        d += __shfl_xor_sync(0xFFFFFFFFu, d, o);
    }
    if (lane == 0) { g_as[gwarp] = s; g_ad[gwarp] = d; }
}

// ---------------- GAT aggregation (scatter-softmax via CSR, +bias, opt relu) ----
__global__ __launch_bounds__(256) void k_gat_agg(const float* __restrict__ Hg,
                                                 float* __restrict__ out,
                                                 const float* __restrict__ bias,
                                                 int do_relu) {
    __shared__ float sm[NHD], ss[NHD];
    int n = blockIdx.x;
    int s0 = g_rowstart[n], s1 = g_rowstart[n + 1];
    int tid = threadIdx.x;

    if (tid < NHD) {
        float adn = g_ad[n * NHD + tid];
        float m = lrelu(g_as[n * NHD + tid] + adn);  // self edge
        for (int j = s0; j < s1; j++) {
            int s = g_csrsrc[j];
            float v = lrelu(g_as[s * NHD + tid] + adn);
            m = fmaxf(m, v);
        }
        float sum = expf(lrelu(g_as[n * NHD + tid] + adn) - m);
        for (int j = s0; j < s1; j++) {
            int s = g_csrsrc[j];
            sum += expf(lrelu(g_as[s * NHD + tid] + adn) - m);
        }
        sm[tid] = m;
        ss[tid] = sum;
    }
    __syncthreads();

    float acc[3];
#pragma unroll
    for (int c = 0; c < 3; c++) {
        int fc = tid + c * 256;
        int h = fc >> 6;
        float adn = g_ad[n * NHD + h];
        float w = expf(lrelu(g_as[n * NHD + h] + adn) - sm[h]) / ss[h];
        acc[c] = Hg[(size_t)n * HH + fc] * w;
    }
    for (int j = s0; j < s1; j++) {
        int s = g_csrsrc[j];
        const float* row = Hg + (size_t)s * HH;
#pragma unroll
        for (int c = 0; c < 3; c++) {
            int fc = tid + c * 256;
            int h = fc >> 6;
            float w = expf(lrelu(g_as[s * NHD + h] + g_ad[n * NHD + h]) - sm[h]) / ss[h];
            acc[c] += row[fc] * w;
        }
    }
    float* o = out + (size_t)n * HH;
#pragma unroll
    for (int c = 0; c < 3; c++) {
        int fc = tid + c * 256;
        float v = acc[c] + bias[fc];
        o[fc] = do_relu ? fmaxf(v, 0.f) : v;
    }
}

// ---------------- global mean pool (sorted batch, binary search ranges) --------
__device__ __forceinline__ int lower_bound_batch(const int* b, int key) {
    int lo = 0, hi = NN;
    while (lo < hi) {
        int mid = (lo + hi) >> 1;
        if (b[mid] < key) lo = mid + 1; else hi = mid;
    }
    return lo;
}

__global__ void k_pool(const float* __restrict__ X, const int* __restrict__ batch) {
    int g = blockIdx.x / 12;
    int chunk = blockIdx.x % 12;
    int lo = lower_bound_batch(batch, g);
    int hi = lower_bound_batch(batch, g + 1);
    int f = chunk * 64 + threadIdx.x;
    float s = 0.f;
    for (int i = lo; i < hi; i++) s += X[(size_t)i * HH + f];
    float c = (float)((hi - lo) > 0 ? (hi - lo) : 1);
    g_pool[g * HH + f] = s / c;
}

// ---------------- classifier MLP ----------------
__global__ void k_mlp1(const float* __restrict__ wc1, const float* __restrict__ bc1) {
    __shared__ float sg[HH];
    int g = blockIdx.x;
    for (int i = threadIdx.x; i < HH; i += H2) sg[i] = g_pool[g * HH + i];
    __syncthreads();
    float acc = bc1[threadIdx.x];
    for (int k = 0; k < HH; k++) acc += sg[k] * wc1[k * H2 + threadIdx.x];
    g_zmlp[g * H2 + threadIdx.x] = fmaxf(acc, 0.f);
}

__global__ void k_mlp2(const float* __restrict__ wc2, const float* __restrict__ bc2,
                       float* __restrict__ out) {
    __shared__ float sz[H2];
    int g = blockIdx.x;
    for (int i = threadIdx.x; i < H2; i += 64) sz[i] = g_zmlp[g * H2 + i];
    __syncthreads();
    if (threadIdx.x < NCL) {
        float acc = bc2[threadIdx.x];
        for (int k = 0; k < H2; k++) acc += sz[k] * wc2[k * NCL + threadIdx.x];
        out[g * NCL + threadIdx.x] = acc;
    }
}

// ---------------- launch ----------------
extern "C" void kernel_launch(void* const* d_in, const int* in_sizes, int n_in,
                              void* d_out, int out_size) {
    const float* x    = (const float*)d_in[0];
    const int*   ei   = (const int*)d_in[1];
    const int*   batc = (const int*)d_in[2];
    const float* w1   = (const float*)d_in[3];
    const float* b1   = (const float*)d_in[4];
    const float* w2   = (const float*)d_in[5];
    const float* b2   = (const float*)d_in[6];
    const float* w3   = (const float*)d_in[7];
    const float* b3   = (const float*)d_in[8];
    const float* wg1  = (const float*)d_in[9];
    const float* as1  = (const float*)d_in[10];
    const float* ad1  = (const float*)d_in[11];
    const float* bg1  = (const float*)d_in[12];
    const float* wg2  = (const float*)d_in[13];
    const float* as2  = (const float*)d_in[14];
    const float* ad2  = (const float*)d_in[15];
    const float* bg2  = (const float*)d_in[16];
    const float* wc1  = (const float*)d_in[17];
    const float* bc1  = (const float*)d_in[18];
    const float* wc2  = (const float*)d_in[19];
    const float* bc2  = (const float*)d_in[20];
    float* out = (float*)d_out;

    float *bufA, *bufB, *bufC;
    cudaGetSymbolAddress((void**)&bufA, g_bufA);
    cudaGetSymbolAddress((void**)&bufB, g_bufB);
    cudaGetSymbolAddress((void**)&bufC, g_bufC);

    dim3 gemm_grid((NN + BM - 1) / BM, HH / BN);

    // CSR build
    k_zero_cnt<<<(NN + 255) / 256, 256>>>();
    k_count<<<(EE + 255) / 256, 256>>>(ei);
    k_scan<<<1, 1024>>>();
    k_dinv<<<(NN + 255) / 256, 256>>>();
    k_fill<<<(EE + 255) / 256, 256>>>(ei);

    // GCN layer 1: x[N,3] -> bufB -> agg -> bufA
    k_lin3<<<NN, 256>>>(x, w1, bufB);
    k_gcn_agg<<<NN, 256>>>(bufB, bufA, b1);

    // GCN layer 2: bufA -> bufB -> agg -> bufC
    k_sgemm<<<gemm_grid, 256>>>(bufA, w2, bufB, NN);
    k_gcn_agg<<<NN, 256>>>(bufB, bufC, b2);

    // GCN layer 3: bufC -> bufB -> agg -> bufA
    k_sgemm<<<gemm_grid, 256>>>(bufC, w3, bufB, NN);
    k_gcn_agg<<<NN, 256>>>(bufB, bufA, b3);

    // GAT layer 1: bufA -> bufB (Hg) ; alpha ; agg -> bufC (relu)
    k_sgemm<<<gemm_grid, 256>>>(bufA, wg1, bufB, NN);
    k_alpha<<<(NN * NHD * 32 + 255) / 256, 256>>>(bufB, as1, ad1);
    k_gat_agg<<<NN, 256>>>(bufB, bufC, bg1, 1);

    // GAT layer 2: bufC -> bufB ; alpha ; agg -> bufA (no relu)
    k_sgemm<<<gemm_grid, 256>>>(bufC, wg2, bufB, NN);
    k_alpha<<<(NN * NHD * 32 + 255) / 256, 256>>>(bufB, as2, ad2);
    k_gat_agg<<<NN, 256>>>(bufB, bufA, bg2, 0);

    // pool + MLP
    k_pool<<<NGR * 12, 64>>>(bufA, batc);
    k_mlp1<<<NGR, H2>>>(wc1, bc1);
    k_mlp2<<<NGR, 64>>>(wc2, bc2, out);
}

// round 2
// speedup vs baseline: 1.0592x; 1.0592x over previous
#include <cuda_runtime.h>
#include <cuda_bf16.h>
#include <math.h>

#define NN 50000
#define EE 100000
#define HH 768
#define NHD 12
#define HDD 64
#define NGR 64
#define NCL 10
#define H2 384

// ---------------- scratch (static device globals; no allocation) ----------------
__device__ float g_bufA[(size_t)NN * HH];
__device__ float g_bufB[(size_t)NN * HH];
__device__ float g_bufC[(size_t)NN * HH];
__device__ float g_dinv[NN];
__device__ int   g_cnt[NN];
__device__ int   g_rowstart[NN + 1];
__device__ int   g_cursor[NN];
__device__ int   g_csrsrc[EE];
__device__ float g_as[NN * NHD];
__device__ float g_ad[NN * NHD];
__device__ float g_pool[NGR * HH];
__device__ float g_zmlp[NGR * H2];

__device__ __forceinline__ float lrelu(float x) { return x > 0.f ? x : 0.2f * x; }

// packed fp32x2 helpers (sm_103a)
__device__ __forceinline__ unsigned long long pack2(float x, float y) {
    unsigned long long r;
    asm("mov.b64 %0, {%1, %2};" : "=l"(r) : "f"(x), "f"(y));
    return r;
}
__device__ __forceinline__ void unpack2(unsigned long long v, float& x, float& y) {
    asm("mov.b64 {%0, %1}, %2;" : "=f"(x), "=f"(y) : "l"(v));
}
__device__ __forceinline__ void ffma2(unsigned long long& d, unsigned long long a,
                                      unsigned long long b) {
    asm("fma.rn.f32x2 %0, %1, %2, %0;" : "+l"(d) : "l"(a), "l"(b));
}

// ---------------- CSR build ----------------
__global__ void k_zero_cnt() {
    int i = blockIdx.x * blockDim.x + threadIdx.x;
    if (i < NN) g_cnt[i] = 0;
}

__global__ void k_count(const int* __restrict__ ei) {
    int e = blockIdx.x * blockDim.x + threadIdx.x;
    if (e < EE) atomicAdd(&g_cnt[ei[EE + e]], 1);
}

__global__ void k_scan() {
    __shared__ int sh[1024];
    int tid = threadIdx.x;
    int off = 0;
    for (int base = 0; base < NN; base += 1024) {
        int i = base + tid;
        int v = (i < NN) ? g_cnt[i] : 0;
        sh[tid] = v;
        __syncthreads();
        for (int s = 1; s < 1024; s <<= 1) {
            int t = (tid >= s) ? sh[tid - s] : 0;
            __syncthreads();
            sh[tid] += t;
            __syncthreads();
        }
        if (i < NN) {
            int excl = off + sh[tid] - v;
            g_rowstart[i] = excl;
            g_cursor[i] = excl;
        }
        int tot = sh[1023];
        __syncthreads();
        off += tot;
    }
    if (tid == 0) g_rowstart[NN] = off;
}

__global__ void k_dinv() {
    int i = blockIdx.x * blockDim.x + threadIdx.x;
    if (i < NN) g_dinv[i] = rsqrtf((float)(g_cnt[i] + 1));
}

__global__ void k_fill(const int* __restrict__ ei) {
    int e = blockIdx.x * blockDim.x + threadIdx.x;
    if (e < EE) {
        int s = ei[e];
        int d = ei[EE + e];
        int pos = atomicAdd(&g_cursor[d], 1);
        g_csrsrc[pos] = s;
    }
}

// ---------------- first-layer linear (K = 3) ----------------
__global__ void k_lin3(const float* __restrict__ x, const float* __restrict__ w,
                       float* __restrict__ T) {
    int n = blockIdx.x;
    float x0 = x[n * 3 + 0], x1 = x[n * 3 + 1], x2 = x[n * 3 + 2];
    for (int f = threadIdx.x; f < HH; f += 256) {
        T[(size_t)n * HH + f] = x0 * w[f] + x1 * w[HH + f] + x2 * w[2 * HH + f];
    }
}

// ---------------- SGEMM: C[M,768] = A[M,768] @ B[768,768] (f32x2 FMA) ----------
#define BM 128
#define BN 128
#define BK 16
__global__ __launch_bounds__(256) void k_sgemm(const float* __restrict__ A,
                                               const float* __restrict__ B,
                                               float* __restrict__ C, int M) {
    __shared__ float As[BK][BM];
    __shared__ float Bs[BK][BN];
    int row0 = blockIdx.x * BM;
    int col0 = blockIdx.y * BN;
    int tid = threadIdx.x;
    int tx = tid & 15, ty = tid >> 4;

    unsigned long long acc2[8][4];
#pragma unroll
    for (int i = 0; i < 8; i++)
#pragma unroll
        for (int j = 0; j < 4; j++) acc2[i][j] = 0ull;

    int arow = tid >> 2;
    int acol = (tid & 3) * 4;
    int brow = tid >> 5;
    int bcol = (tid & 31) * 4;

    // register prefetch buffers
    float4 pa[2], pb[2];
#pragma unroll
    for (int r = 0; r < 2; r++) {
        int gr = row0 + arow + r * 64;
        pa[r] = (gr < M) ? *(const float4*)&A[(size_t)gr * HH + acol]
                         : make_float4(0.f, 0.f, 0.f, 0.f);
        int gk = brow + r * 8;
        pb[r] = *(const float4*)&B[(size_t)gk * HH + col0 + bcol];
    }

    for (int k0 = 0; k0 < HH; k0 += BK) {
#pragma unroll
        for (int r = 0; r < 2; r++) {
            As[acol + 0][arow + r * 64] = pa[r].x;
            As[acol + 1][arow + r * 64] = pa[r].y;
            As[acol + 2][arow + r * 64] = pa[r].z;
            As[acol + 3][arow + r * 64] = pa[r].w;
            *(float4*)&Bs[brow + r * 8][bcol] = pb[r];
        }
        __syncthreads();

        if (k0 + BK < HH) {
            int k1 = k0 + BK;
#pragma unroll
            for (int r = 0; r < 2; r++) {
                int gr = row0 + arow + r * 64;
                pa[r] = (gr < M) ? *(const float4*)&A[(size_t)gr * HH + k1 + acol]
                                 : make_float4(0.f, 0.f, 0.f, 0.f);
                int gk = k1 + brow + r * 8;
                pb[r] = *(const float4*)&B[(size_t)gk * HH + col0 + bcol];
            }
        }

#pragma unroll
        for (int kk = 0; kk < BK; kk++) {
            float a[8];
            *(float4*)&a[0] = *(const float4*)&As[kk][ty * 8];
            *(float4*)&a[4] = *(const float4*)&As[kk][ty * 8 + 4];
            float4 bq0 = *(const float4*)&Bs[kk][tx * 8];
            float4 bq1 = *(const float4*)&Bs[kk][tx * 8 + 4];
            unsigned long long b2[4];
            b2[0] = pack2(bq0.x, bq0.y);
            b2[1] = pack2(bq0.z, bq0.w);
            b2[2] = pack2(bq1.x, bq1.y);
            b2[3] = pack2(bq1.z, bq1.w);
#pragma unroll
            for (int i = 0; i < 8; i++) {
                unsigned long long a2 = pack2(a[i], a[i]);
#pragma unroll
                for (int j = 0; j < 4; j++) ffma2(acc2[i][j], a2, b2[j]);
            }
        }
        __syncthreads();
    }

#pragma unroll
    for (int i = 0; i < 8; i++) {
        int gr = row0 + ty * 8 + i;
        if (gr < M) {
            float o[8];
#pragma unroll
            for (int j = 0; j < 4; j++) unpack2(acc2[i][j], o[2 * j], o[2 * j + 1]);
            *(float4*)&C[(size_t)gr * HH + col0 + tx * 8] = *(float4*)&o[0];
            *(float4*)&C[(size_t)gr * HH + col0 + tx * 8 + 4] = *(float4*)&o[4];
        }
    }
}

// ---------------- GCN aggregation (+bias+relu) ----------------
__global__ __launch_bounds__(256) void k_gcn_agg(const float* __restrict__ T,
                                                 float* __restrict__ out,
                                                 const float* __restrict__ bias) {
    int n = blockIdx.x;
    float din = g_dinv[n];
    int s0 = g_rowstart[n], s1 = g_rowstart[n + 1];
    int f = threadIdx.x;
    float selfw = din * din;
    const float* rn = T + (size_t)n * HH;
    float a0 = rn[f] * selfw;
    float a1 = rn[f + 256] * selfw;
    float a2 = rn[f + 512] * selfw;
    for (int j = s0; j < s1; j++) {
        int s = g_csrsrc[j];
        float w = g_dinv[s] * din;
        const float* row = T + (size_t)s * HH;
        a0 += row[f] * w;
        a1 += row[f + 256] * w;
        a2 += row[f + 512] * w;
    }
    a0 += bias[f]; a1 += bias[f + 256]; a2 += bias[f + 512];
    float* o = out + (size_t)n * HH;
    o[f] = fmaxf(a0, 0.f);
    o[f + 256] = fmaxf(a1, 0.f);
    o[f + 512] = fmaxf(a2, 0.f);
}

// ---------------- GAT alpha (per node, per head dot products) ----------------
__global__ void k_alpha(const float* __restrict__ Hg, const float* __restrict__ a_src,
                        const float* __restrict__ a_dst) {
    int gwarp = (blockIdx.x * blockDim.x + threadIdx.x) >> 5;
    int lane = threadIdx.x & 31;
    if (gwarp >= NN * NHD) return;
    int n = gwarp / NHD, h = gwarp % NHD;
    const float* row = Hg + (size_t)n * HH + h * HDD;
    float v0 = row[lane], v1 = row[lane + 32];
    float s = v0 * a_src[h * HDD + lane] + v1 * a_src[h * HDD + lane + 32];
    float d = v0 * a_dst[h * HDD + lane] + v1 * a_dst[h * HDD + lane + 32];
#pragma unroll
    for (int o = 16; o; o >>= 1) {
        s += __shfl_xor_sync(0xFFFFFFFFu, s, o);
        d += __shfl_xor_sync(0xFFFFFFFFu, d, o);
    }
    if (lane == 0) { g_as[gwarp] = s; g_ad[gwarp] = d; }
}

// ---------------- GAT aggregation (per-(edge,head) softmax weights in smem) ----
#define CH 20
__global__ __launch_bounds__(256) void k_gat_agg(const float* __restrict__ Hg,
                                                 float* __restrict__ out,
                                                 const float* __restrict__ bias,
                                                 int do_relu) {
    __shared__ float sm[NHD], ssi[NHD], sself[NHD];
    __shared__ float swgt[CH][NHD];
    int n = blockIdx.x;
    int s0 = g_rowstart[n], s1 = g_rowstart[n + 1];
    int tid = threadIdx.x;

    if (tid < NHD) {
        float adn = g_ad[n * NHD + tid];
        float e_self = lrelu(g_as[n * NHD + tid] + adn);
        float m = e_self;
        for (int j = s0; j < s1; j++) {
            int s = g_csrsrc[j];
            float v = lrelu(g_as[s * NHD + tid] + adn);
            m = fmaxf(m, v);
        }
        float sum = __expf(e_self - m);
        for (int j = s0; j < s1; j++) {
            int s = g_csrsrc[j];
            sum += __expf(lrelu(g_as[s * NHD + tid] + adn) - m);
        }
        float inv = 1.0f / sum;
        sm[tid] = m;
        ssi[tid] = inv;
        sself[tid] = __expf(e_self - m) * inv;
    }
    __syncthreads();

    int h0 = tid >> 6;          // head for feature tid
    int h1 = (tid + 256) >> 6;
    int h2 = (tid + 512) >> 6;
    const float* rn = Hg + (size_t)n * HH;
    float acc0 = rn[tid] * sself[h0];
    float acc1 = rn[tid + 256] * sself[h1];
    float acc2v = rn[tid + 512] * sself[h2];

    for (int j0 = s0; j0 < s1; j0 += CH) {
        int cnt = min(CH, s1 - j0);
        if (tid < cnt * NHD) {
            int jj = tid / NHD, h = tid % NHD;
            int s = g_csrsrc[j0 + jj];
            swgt[jj][h] =
                __expf(lrelu(g_as[s * NHD + h] + g_ad[n * NHD + h]) - sm[h]) * ssi[h];
        }
        __syncthreads();
        for (int jj = 0; jj < cnt; jj++) {
            int s = g_csrsrc[j0 + jj];
            const float* row = Hg + (size_t)s * HH;
            acc0 += row[tid] * swgt[jj][h0];
            acc1 += row[tid + 256] * swgt[jj][h1];
            acc2v += row[tid + 512] * swgt[jj][h2];
        }
        __syncthreads();
    }

    float* o = out + (size_t)n * HH;
    float v0 = acc0 + bias[tid];
    float v1 = acc1 + bias[tid + 256];
    float v2 = acc2v + bias[tid + 512];
    if (do_relu) { v0 = fmaxf(v0, 0.f); v1 = fmaxf(v1, 0.f); v2 = fmaxf(v2, 0.f); }
    o[tid] = v0;
    o[tid + 256] = v1;
    o[tid + 512] = v2;
}

// ---------------- global mean pool (sorted batch, binary search ranges) --------
__device__ __forceinline__ int lower_bound_batch(const int* b, int key) {
    int lo = 0, hi = NN;
    while (lo < hi) {
        int mid = (lo + hi) >> 1;
        if (b[mid] < key) lo = mid + 1; else hi = mid;
    }
    return lo;
}

__global__ void k_pool(const float* __restrict__ X, const int* __restrict__ batch) {
    int g = blockIdx.x / 12;
    int chunk = blockIdx.x % 12;
    int lo = lower_bound_batch(batch, g);
    int hi = lower_bound_batch(batch, g + 1);
    int f = chunk * 64 + threadIdx.x;
    float s = 0.f;
    for (int i = lo; i < hi; i++) s += X[(size_t)i * HH + f];
    float c = (float)((hi - lo) > 0 ? (hi - lo) : 1);
    g_pool[g * HH + f] = s / c;
}

// ---------------- classifier MLP ----------------
__global__ void k_mlp1(const float* __restrict__ wc1, const float* __restrict__ bc1) {
    __shared__ float sg[HH];
    int g = blockIdx.x;
    for (int i = threadIdx.x; i < HH; i += H2) sg[i] = g_pool[g * HH + i];
    __syncthreads();
    float acc = bc1[threadIdx.x];
    for (int k = 0; k < HH; k++) acc += sg[k] * wc1[k * H2 + threadIdx.x];
    g_zmlp[g * H2 + threadIdx.x] = fmaxf(acc, 0.f);
}

__global__ void k_mlp2(const float* __restrict__ wc2, const float* __restrict__ bc2,
                       float* __restrict__ out) {
    __shared__ float sz[H2];
    int g = blockIdx.x;
    for (int i = threadIdx.x; i < H2; i += 64) sz[i] = g_zmlp[g * H2 + i];
    __syncthreads();
    if (threadIdx.x < NCL) {
        float acc = bc2[threadIdx.x];
        for (int k = 0; k < H2; k++) acc += sz[k] * wc2[k * NCL + threadIdx.x];
        out[g * NCL + threadIdx.x] = acc;
    }
}

// ---------------- launch ----------------
extern "C" void kernel_launch(void* const* d_in, const int* in_sizes, int n_in,
                              void* d_out, int out_size) {
    const float* x    = (const float*)d_in[0];
    const int*   ei   = (const int*)d_in[1];
    const int*   batc = (const int*)d_in[2];
    const float* w1   = (const float*)d_in[3];
    const float* b1   = (const float*)d_in[4];
    const float* w2   = (const float*)d_in[5];
    const float* b2   = (const float*)d_in[6];
    const float* w3   = (const float*)d_in[7];
    const float* b3   = (const float*)d_in[8];
    const float* wg1  = (const float*)d_in[9];
    const float* as1  = (const float*)d_in[10];
    const float* ad1  = (const float*)d_in[11];
    const float* bg1  = (const float*)d_in[12];
    const float* wg2  = (const float*)d_in[13];
    const float* as2  = (const float*)d_in[14];
    const float* ad2  = (const float*)d_in[15];
    const float* bg2  = (const float*)d_in[16];
    const float* wc1  = (const float*)d_in[17];
    const float* bc1  = (const float*)d_in[18];
    const float* wc2  = (const float*)d_in[19];
    const float* bc2  = (const float*)d_in[20];
    float* out = (float*)d_out;

    float *bufA, *bufB, *bufC;
    cudaGetSymbolAddress((void**)&bufA, g_bufA);
    cudaGetSymbolAddress((void**)&bufB, g_bufB);
    cudaGetSymbolAddress((void**)&bufC, g_bufC);

    dim3 gemm_grid((NN + BM - 1) / BM, HH / BN);

    // CSR build
    k_zero_cnt<<<(NN + 255) / 256, 256>>>();
    k_count<<<(EE + 255) / 256, 256>>>(ei);
    k_scan<<<1, 1024>>>();
    k_dinv<<<(NN + 255) / 256, 256>>>();
    k_fill<<<(EE + 255) / 256, 256>>>(ei);

    // GCN layer 1: x[N,3] -> bufB -> agg -> bufA
    k_lin3<<<NN, 256>>>(x, w1, bufB);
    k_gcn_agg<<<NN, 256>>>(bufB, bufA, b1);

    // GCN layer 2: bufA -> bufB -> agg -> bufC
    k_sgemm<<<gemm_grid, 256>>>(bufA, w2, bufB, NN);
    k_gcn_agg<<<NN, 256>>>(bufB, bufC, b2);

    // GCN layer 3: bufC -> bufB -> agg -> bufA
    k_sgemm<<<gemm_grid, 256>>>(bufC, w3, bufB, NN);
    k_gcn_agg<<<NN, 256>>>(bufB, bufA, b3);

    // GAT layer 1: bufA -> bufB (Hg) ; alpha ; agg -> bufC (relu)
    k_sgemm<<<gemm_grid, 256>>>(bufA, wg1, bufB, NN);
    k_alpha<<<(NN * NHD * 32 + 255) / 256, 256>>>(bufB, as1, ad1);
    k_gat_agg<<<NN, 256>>>(bufB, bufC, bg1, 1);

    // GAT layer 2: bufC -> bufB ; alpha ; agg -> bufA (no relu)
    k_sgemm<<<gemm_grid, 256>>>(bufC, wg2, bufB, NN);
    k_alpha<<<(NN * NHD * 32 + 255) / 256, 256>>>(bufB, as2, ad2);
    k_gat_agg<<<NN, 256>>>(bufB, bufA, bg2, 0);

    // pool + MLP
    k_pool<<<NGR * 12, 64>>>(bufA, batc);
    k_mlp1<<<NGR, H2>>>(wc1, bc1);
    k_mlp2<<<NGR, 64>>>(wc2, bc2, out);
}

// round 6
// speedup vs baseline: 1.8784x; 1.7734x over previous
#include <cuda_runtime.h>
#include <cuda_bf16.h>
#include <math.h>
#include <stdint.h>

#define NN 50000
#define EE 100000
#define HH 768
#define NHD 12
#define HDD 64
#define NGR 64
#define NCL 10
#define H2 384

// ---------------- scratch (static device globals; no allocation) ----------------
__device__ float g_bufA[(size_t)NN * HH];
__device__ float g_bufB[(size_t)NN * HH];
__device__ float g_bufC[(size_t)NN * HH];
__device__ __nv_bfloat16 g_Ah[(size_t)NN * HH];
__device__ __nv_bfloat16 g_Al[(size_t)NN * HH];
__device__ __nv_bfloat16 g_Wh[(size_t)HH * HH];   // transposed: [N=768][K=768]
__device__ __nv_bfloat16 g_Wl[(size_t)HH * HH];
__device__ float g_dinv[NN];
__device__ int   g_cnt[NN];
__device__ int   g_rowstart[NN + 1];
__device__ int   g_cursor[NN];
__device__ int   g_csrsrc[EE];
__device__ float g_as[NN * NHD];
__device__ float g_ad[NN * NHD];
__device__ float g_pool[NGR * HH];
__device__ float g_zmlp[NGR * H2];

__device__ __forceinline__ float lrelu(float x) { return x > 0.f ? x : 0.2f * x; }

// ---------------- CSR build ----------------
__global__ void k_zero_cnt() {
    int i = blockIdx.x * blockDim.x + threadIdx.x;
    if (i < NN) g_cnt[i] = 0;
}

__global__ void k_count(const int* __restrict__ ei) {
    int e = blockIdx.x * blockDim.x + threadIdx.x;
    if (e < EE) atomicAdd(&g_cnt[ei[EE + e]], 1);
}

__global__ void k_scan() {
    __shared__ int sh[1024];
    int tid = threadIdx.x;
    int off = 0;
    for (int base = 0; base < NN; base += 1024) {
        int i = base + tid;
        int v = (i < NN) ? g_cnt[i] : 0;
        sh[tid] = v;
        __syncthreads();
        for (int s = 1; s < 1024; s <<= 1) {
            int t = (tid >= s) ? sh[tid - s] : 0;
            __syncthreads();
            sh[tid] += t;
            __syncthreads();
        }
        if (i < NN) {
            int excl = off + sh[tid] - v;
            g_rowstart[i] = excl;
            g_cursor[i] = excl;
        }
        int tot = sh[1023];
        __syncthreads();
        off += tot;
    }
    if (tid == 0) g_rowstart[NN] = off;
}

__global__ void k_dinv() {
    int i = blockIdx.x * blockDim.x + threadIdx.x;
    if (i < NN) g_dinv[i] = rsqrtf((float)(g_cnt[i] + 1));
}

__global__ void k_fill(const int* __restrict__ ei) {
    int e = blockIdx.x * blockDim.x + threadIdx.x;
    if (e < EE) {
        int s = ei[e];
        int d = ei[EE + e];
        int pos = atomicAdd(&g_cursor[d], 1);
        g_csrsrc[pos] = s;
    }
}

// ---------------- first-layer linear (K = 3) ----------------
__global__ void k_lin3(const float* __restrict__ x, const float* __restrict__ w,
                       float* __restrict__ T) {
    int n = blockIdx.x;
    float x0 = x[n * 3 + 0], x1 = x[n * 3 + 1], x2 = x[n * 3 + 2];
    for (int f = threadIdx.x; f < HH; f += 256) {
        T[(size_t)n * HH + f] = x0 * w[f] + x1 * w[HH + f] + x2 * w[2 * HH + f];
    }
}

// ---------------- split conversions (error-compensated bf16) ----------------
__global__ void k_split_a(const float* __restrict__ X,
                          __nv_bfloat16* __restrict__ hi,
                          __nv_bfloat16* __restrict__ lo) {
    size_t i = ((size_t)blockIdx.x * blockDim.x + threadIdx.x) * 4;
    float4 v = *(const float4*)(X + i);
    __nv_bfloat16 h0 = __float2bfloat16(v.x);
    __nv_bfloat16 h1 = __float2bfloat16(v.y);
    __nv_bfloat16 h2 = __float2bfloat16(v.z);
    __nv_bfloat16 h3 = __float2bfloat16(v.w);
    __nv_bfloat16 l0 = __float2bfloat16(v.x - __bfloat162float(h0));
    __nv_bfloat16 l1 = __float2bfloat16(v.y - __bfloat162float(h1));
    __nv_bfloat16 l2 = __float2bfloat16(v.z - __bfloat162float(h2));
    __nv_bfloat16 l3 = __float2bfloat16(v.w - __bfloat162float(h3));
    *(__nv_bfloat162*)(hi + i) = __nv_bfloat162(h0, h1);
    *(__nv_bfloat162*)(hi + i + 2) = __nv_bfloat162(h2, h3);
    *(__nv_bfloat162*)(lo + i) = __nv_bfloat162(l0, l1);
    *(__nv_bfloat162*)(lo + i + 2) = __nv_bfloat162(l2, l3);
}

// transpose + split weights: out[n*768+k] = w[k*768+n]
__global__ void k_split_w(const float* __restrict__ w,
                          __nv_bfloat16* __restrict__ th,
                          __nv_bfloat16* __restrict__ tl) {
    int idx = blockIdx.x * 256 + threadIdx.x;
    int n = idx / HH, k = idx % HH;
    float v = w[(size_t)k * HH + n];
    __nv_bfloat16 h = __float2bfloat16(v);
    th[idx] = h;
    tl[idx] = __float2bfloat16(v - __bfloat162float(h));
}

// ---------------- mma.sync GEMM: C[M,768] = A[M,768] @ W[768,768] --------------
// A as hi/lo bf16 [M,768]; W transposed hi/lo bf16 [768(N),768(K)].
// acc += Ah*Bh + Ah*Bl + Al*Bh  (fp32 accumulators)
#define GBM 128
#define GBN 128
#define GBK 32
#define KIT (HH / GBK)          // 24
#define TROW 40                 // padded row (bf16 elems): 80 bytes
#define TSZ (GBM * TROW)        // 5120 bf16 elems per tile
#define MMA_SMEM (8 * TSZ * 2)  // 81920 bytes: [2 bufs][4 tensors]

__device__ __forceinline__ void ldsm4(uint32_t* r, uint32_t addr) {
    asm volatile("ldmatrix.sync.aligned.m8n8.x4.shared.b16 {%0,%1,%2,%3}, [%4];"
                 : "=r"(r[0]), "=r"(r[1]), "=r"(r[2]), "=r"(r[3]) : "r"(addr));
}
__device__ __forceinline__ void mma16816(float* c, const uint32_t* a, uint32_t b0,
                                         uint32_t b1) {
    asm volatile(
        "mma.sync.aligned.m16n8k16.row.col.f32.bf16.bf16.f32 "
        "{%0,%1,%2,%3}, {%4,%5,%6,%7}, {%8,%9}, {%0,%1,%2,%3};"
        : "+f"(c[0]), "+f"(c[1]), "+f"(c[2]), "+f"(c[3])
        : "r"(a[0]), "r"(a[1]), "r"(a[2]), "r"(a[3]), "r"(b0), "r"(b1));
}
__device__ __forceinline__ void cpa16(uint32_t dst, const void* src, int sz) {
    asm volatile("cp.async.ca.shared.global [%0], [%1], 16, %2;"
                 :: "r"(dst), "l"(src), "r"(sz) : "memory");
}

__global__ __launch_bounds__(256) void k_mma_gemm(const __nv_bfloat16* __restrict__ Ah,
                                                  const __nv_bfloat16* __restrict__ Al,
                                                  const __nv_bfloat16* __restrict__ Bh,
                                                  const __nv_bfloat16* __restrict__ Bl,
                                                  float* __restrict__ C) {
    extern __shared__ char smem[];
    uint32_t sb;
    asm("{ .reg .u64 t; cvta.to.shared.u64 t, %1; cvt.u32.u64 %0, t; }"
        : "=r"(sb) : "l"(smem));
    int tid = threadIdx.x;
    int lane = tid & 31, wid = tid >> 5;
    int wm = wid & 1, wn = wid >> 1;
    int row0 = blockIdx.x * GBM;
    int col0 = blockIdx.y * GBN;

    float acc[4][4][4];
#pragma unroll
    for (int i = 0; i < 4; i++)
#pragma unroll
        for (int j = 0; j < 4; j++)
#pragma unroll
            for (int q = 0; q < 4; q++) acc[i][j][q] = 0.f;

    int vr = tid >> 2;          // row handled by this thread's vectors
    int vc = (tid & 3) * 8;     // bf16 col within 32-wide chunk
    int grA = row0 + vr;
    int okA = (grA < NN) ? 16 : 0;
    const char* pAh0 = (const char*)(Ah + (size_t)(okA ? grA : 0) * HH + vc);
    const char* pAl0 = (const char*)(Al + (size_t)(okA ? grA : 0) * HH + vc);
    const char* pBh0 = (const char*)(Bh + (size_t)(col0 + vr) * HH + vc);
    const char* pBl0 = (const char*)(Bl + (size_t)(col0 + vr) * HH + vc);
    int grA2 = row0 + vr + 64;
    int okA2 = (grA2 < NN) ? 16 : 0;
    const char* pAh1 = (const char*)(Ah + (size_t)(okA2 ? grA2 : 0) * HH + vc);
    const char* pAl1 = (const char*)(Al + (size_t)(okA2 ? grA2 : 0) * HH + vc);
    const char* pBh1 = (const char*)(Bh + (size_t)(col0 + vr + 64) * HH + vc);
    const char* pBl1 = (const char*)(Bl + (size_t)(col0 + vr + 64) * HH + vc);
    uint32_t d0 = sb + (vr * TROW + vc) * 2;
    uint32_t d1 = sb + ((vr + 64) * TROW + vc) * 2;

#define LOAD_TILES(buf, kbyte)                                                  \
    do {                                                                        \
        uint32_t bo = (buf) * (4 * TSZ * 2);                                    \
        cpa16(bo + d0 + 0 * TSZ * 2, pAh0 + (kbyte), okA);                      \
        cpa16(bo + d1 + 0 * TSZ * 2, pAh1 + (kbyte), okA2);                     \
        cpa16(bo + d0 + 1 * TSZ * 2, pAl0 + (kbyte), okA);                      \
        cpa16(bo + d1 + 1 * TSZ * 2, pAl1 + (kbyte), okA2);                     \
        cpa16(bo + d0 + 2 * TSZ * 2, pBh0 + (kbyte), 16);                       \
        cpa16(bo + d1 + 2 * TSZ * 2, pBh1 + (kbyte), 16);                       \
        cpa16(bo + d0 + 3 * TSZ * 2, pBl0 + (kbyte), 16);                       \
        cpa16(bo + d1 + 3 * TSZ * 2, pBl1 + (kbyte), 16);                       \
        asm volatile("cp.async.commit_group;" ::: "memory");                    \
    } while (0)

    LOAD_TILES(0, 0);

    int ar = lane & 15;
    int kc = (lane >> 4) * 8;

    for (int kt = 0; kt < KIT; kt++) {
        if (kt + 1 < KIT) LOAD_TILES((kt + 1) & 1, (kt + 1) * GBK * 2);
        if (kt + 1 < KIT)
            asm volatile("cp.async.wait_group 1;" ::: "memory");
        else
            asm volatile("cp.async.wait_group 0;" ::: "memory");
        __syncthreads();

        uint32_t tb = sb + (kt & 1) * (4 * TSZ * 2);
#pragma unroll
        for (int ks = 0; ks < 2; ks++) {
            int kb = ks * 16 + kc;
            uint32_t bh[2][4], bl_[2][4], af[4][4];
#pragma unroll
            for (int nb = 0; nb < 2; nb++) {
                uint32_t addr =
                    tb + 2 * TSZ * 2 + ((wn * 32 + nb * 16 + ar) * TROW + kb) * 2;
                ldsm4(bh[nb], addr);
                ldsm4(bl_[nb], addr + TSZ * 2);
            }
#pragma unroll
            for (int mf = 0; mf < 4; mf++)
                ldsm4(af[mf], tb + ((wm * 64 + mf * 16 + ar) * TROW + kb) * 2);
#pragma unroll
            for (int mf = 0; mf < 4; mf++)
#pragma unroll
                for (int nb = 0; nb < 2; nb++)
#pragma unroll
                    for (int h = 0; h < 2; h++) {
                        float* cc = acc[mf][nb * 2 + h];
                        mma16816(cc, af[mf], bh[nb][h], bh[nb][h + 2]);
                        mma16816(cc, af[mf], bl_[nb][h], bl_[nb][h + 2]);
                    }
#pragma unroll
            for (int mf = 0; mf < 4; mf++)
                ldsm4(af[mf],
                      tb + TSZ * 2 + ((wm * 64 + mf * 16 + ar) * TROW + kb) * 2);
#pragma unroll
            for (int mf = 0; mf < 4; mf++)
#pragma unroll
                for (int nb = 0; nb < 2; nb++)
#pragma unroll
                    for (int h = 0; h < 2; h++)
                        mma16816(acc[mf][nb * 2 + h], af[mf], bh[nb][h],
                                 bh[nb][h + 2]);
        }
        __syncthreads();
    }

    // epilogue: stage each 128x32 column block in smem, store coalesced
    float* stage = (float*)smem;
    for (int cb = 0; cb < 4; cb++) {
        if (wn == cb) {
            int r0r = wm * 64 + (lane >> 2);
            int c0c = (lane & 3) * 2;
#pragma unroll
            for (int mf = 0; mf < 4; mf++)
#pragma unroll
                for (int nf = 0; nf < 4; nf++) {
                    float* cc = acc[mf][nf];
                    int rr = r0r + mf * 16;
                    int ccol = nf * 8 + c0c;
                    stage[rr * 33 + ccol] = cc[0];
                    stage[rr * 33 + ccol + 1] = cc[1];
                    stage[(rr + 8) * 33 + ccol] = cc[2];
                    stage[(rr + 8) * 33 + ccol + 1] = cc[3];
                }
        }
        __syncthreads();
#pragma unroll
        for (int j = 0; j < 16; j++) {
            int e = tid + 256 * j;
            int rr = e >> 5, ccol = e & 31;
            int gr = row0 + rr;
            if (gr < NN)
                C[(size_t)gr * HH + col0 + cb * 32 + ccol] = stage[rr * 33 + ccol];
        }
        __syncthreads();
    }
}

// ---------------- GCN aggregation (+bias+relu) ----------------
__global__ __launch_bounds__(256) void k_gcn_agg(const float* __restrict__ T,
                                                 float* __restrict__ out,
                                                 const float* __restrict__ bias) {
    int n = blockIdx.x;
    float din = g_dinv[n];
    int s0 = g_rowstart[n], s1 = g_rowstart[n + 1];
    int f = threadIdx.x;
    float selfw = din * din;
    const float* rn = T + (size_t)n * HH;
    float a0 = rn[f] * selfw;
    float a1 = rn[f + 256] * selfw;
    float a2 = rn[f + 512] * selfw;
    for (int j = s0; j < s1; j++) {
        int s = g_csrsrc[j];
        float w = g_dinv[s] * din;
        const float* row = T + (size_t)s * HH;
        a0 += row[f] * w;
        a1 += row[f + 256] * w;
        a2 += row[f + 512] * w;
    }
    a0 += bias[f]; a1 += bias[f + 256]; a2 += bias[f + 512];
    float* o = out + (size_t)n * HH;
    o[f] = fmaxf(a0, 0.f);
    o[f + 256] = fmaxf(a1, 0.f);
    o[f + 512] = fmaxf(a2, 0.f);
}

// ---------------- GAT alpha (per node, per head dot products) ----------------
__global__ void k_alpha(const float* __restrict__ Hg, const float* __restrict__ a_src,
                        const float* __restrict__ a_dst) {
    int gwarp = (blockIdx.x * blockDim.x + threadIdx.x) >> 5;
    int lane = threadIdx.x & 31;
    if (gwarp >= NN * NHD) return;
    int n = gwarp / NHD, h = gwarp % NHD;
    const float* row = Hg + (size_t)n * HH + h * HDD;
    float v0 = row[lane], v1 = row[lane + 32];
    float s = v0 * a_src[h * HDD + lane] + v1 * a_src[h * HDD + lane + 32];
    float d = v0 * a_dst[h * HDD + lane] + v1 * a_dst[h * HDD + lane + 32];
#pragma unroll
    for (int o = 16; o; o >>= 1) {
        s += __shfl_xor_sync(0xFFFFFFFFu, s, o);
        d += __shfl_xor_sync(0xFFFFFFFFu, d, o);
    }
    if (lane == 0) { g_as[gwarp] = s; g_ad[gwarp] = d; }
}

// ---------------- GAT aggregation (per-(edge,head) softmax weights in smem) ----
#define CH 20
__global__ __launch_bounds__(256) void k_gat_agg(const float* __restrict__ Hg,
                                                 float* __restrict__ out,
                                                 const float* __restrict__ bias,
                                                 int do_relu) {
    __shared__ float sm[NHD], ssi[NHD], sself[NHD];
    __shared__ float swgt[CH][NHD];
    int n = blockIdx.x;
    int s0 = g_rowstart[n], s1 = g_rowstart[n + 1];
    int tid = threadIdx.x;

    if (tid < NHD) {
        float adn = g_ad[n * NHD + tid];
        float e_self = lrelu(g_as[n * NHD + tid] + adn);
        float m = e_self;
        for (int j = s0; j < s1; j++) {
            int s = g_csrsrc[j];
            float v = lrelu(g_as[s * NHD + tid] + adn);
            m = fmaxf(m, v);
        }
        float sum = __expf(e_self - m);
        for (int j = s0; j < s1; j++) {
            int s = g_csrsrc[j];
            sum += __expf(lrelu(g_as[s * NHD + tid] + adn) - m);
        }
        float inv = 1.0f / sum;
        sm[tid] = m;
        ssi[tid] = inv;
        sself[tid] = __expf(e_self - m) * inv;
    }
    __syncthreads();

    int h0 = tid >> 6;
    int h1 = (tid + 256) >> 6;
    int h2 = (tid + 512) >> 6;
    const float* rn = Hg + (size_t)n * HH;
    float acc0 = rn[tid] * sself[h0];
    float acc1 = rn[tid + 256] * sself[h1];
    float acc2v = rn[tid + 512] * sself[h2];

    for (int j0 = s0; j0 < s1; j0 += CH) {
        int cnt = min(CH, s1 - j0);
        if (tid < cnt * NHD) {
            int jj = tid / NHD, h = tid % NHD;
            int s = g_csrsrc[j0 + jj];
            swgt[jj][h] =
                __expf(lrelu(g_as[s * NHD + h] + g_ad[n * NHD + h]) - sm[h]) * ssi[h];
        }
        __syncthreads();
        for (int jj = 0; jj < cnt; jj++) {
            int s = g_csrsrc[j0 + jj];
            const float* row = Hg + (size_t)s * HH;
            acc0 += row[tid] * swgt[jj][h0];
            acc1 += row[tid + 256] * swgt[jj][h1];
            acc2v += row[tid + 512] * swgt[jj][h2];
        }
        __syncthreads();
    }

    float* o = out + (size_t)n * HH;
    float v0 = acc0 + bias[tid];
    float v1 = acc1 + bias[tid + 256];
    float v2 = acc2v + bias[tid + 512];
    if (do_relu) { v0 = fmaxf(v0, 0.f); v1 = fmaxf(v1, 0.f); v2 = fmaxf(v2, 0.f); }
    o[tid] = v0;
    o[tid + 256] = v1;
    o[tid + 512] = v2;
}

// ---------------- global mean pool (sorted batch, binary search ranges) --------
__device__ __forceinline__ int lower_bound_batch(const int* b, int key) {
    int lo = 0, hi = NN;
    while (lo < hi) {
        int mid = (lo + hi) >> 1;
        if (b[mid] < key) lo = mid + 1; else hi = mid;
    }
    return lo;
}

__global__ void k_pool(const float* __restrict__ X, const int* __restrict__ batch) {
    int g = blockIdx.x / 12;
    int chunk = blockIdx.x % 12;
    int lo = lower_bound_batch(batch, g);
    int hi = lower_bound_batch(batch, g + 1);
    int f = chunk * 64 + threadIdx.x;
    float s = 0.f;
    for (int i = lo; i < hi; i++) s += X[(size_t)i * HH + f];
    float c = (float)((hi - lo) > 0 ? (hi - lo) : 1);
    g_pool[g * HH + f] = s / c;
}

// ---------------- classifier MLP ----------------
__global__ void k_mlp1(const float* __restrict__ wc1, const float* __restrict__ bc1) {
    __shared__ float sg[HH];
    int g = blockIdx.x;
    for (int i = threadIdx.x; i < HH; i += H2) sg[i] = g_pool[g * HH + i];
    __syncthreads();
    float acc = bc1[threadIdx.x];
    for (int k = 0; k < HH; k++) acc += sg[k] * wc1[k * H2 + threadIdx.x];
    g_zmlp[g * H2 + threadIdx.x] = fmaxf(acc, 0.f);
}

__global__ void k_mlp2(const float* __restrict__ wc2, const float* __restrict__ bc2,
                       float* __restrict__ out) {
    __shared__ float sz[H2];
    int g = blockIdx.x;
    for (int i = threadIdx.x; i < H2; i += 64) sz[i] = g_zmlp[g * H2 + i];
    __syncthreads();
    if (threadIdx.x < NCL) {
        float acc = bc2[threadIdx.x];
        for (int k = 0; k < H2; k++) acc += sz[k] * wc2[k * NCL + threadIdx.x];
        out[g * NCL + threadIdx.x] = acc;
    }
}

// ---------------- launch ----------------
extern "C" void kernel_launch(void* const* d_in, const int* in_sizes, int n_in,
                              void* d_out, int out_size) {
    const float* x    = (const float*)d_in[0];
    const int*   ei   = (const int*)d_in[1];
    const int*   batc = (const int*)d_in[2];
    const float* w1   = (const float*)d_in[3];
    const float* b1   = (const float*)d_in[4];
    const float* w2   = (const float*)d_in[5];
    const float* b2   = (const float*)d_in[6];
    const float* w3   = (const float*)d_in[7];
    const float* b3   = (const float*)d_in[8];
    const float* wg1  = (const float*)d_in[9];
    const float* as1  = (const float*)d_in[10];
    const float* ad1  = (const float*)d_in[11];
    const float* bg1  = (const float*)d_in[12];
    const float* wg2  = (const float*)d_in[13];
    const float* as2  = (const float*)d_in[14];
    const float* ad2  = (const float*)d_in[15];
    const float* bg2  = (const float*)d_in[16];
    const float* wc1  = (const float*)d_in[17];
    const float* bc1  = (const float*)d_in[18];
    const float* wc2  = (const float*)d_in[19];
    const float* bc2  = (const float*)d_in[20];
    float* out = (float*)d_out;

    float *bufA, *bufB, *bufC;
    __nv_bfloat16 *Ah, *Al, *Wh, *Wl;
    cudaGetSymbolAddress((void**)&bufA, g_bufA);
    cudaGetSymbolAddress((void**)&bufB, g_bufB);
    cudaGetSymbolAddress((void**)&bufC, g_bufC);
    cudaGetSymbolAddress((void**)&Ah, g_Ah);
    cudaGetSymbolAddress((void**)&Al, g_Al);
    cudaGetSymbolAddress((void**)&Wh, g_Wh);
    cudaGetSymbolAddress((void**)&Wl, g_Wl);

    cudaFuncSetAttribute(k_mma_gemm, cudaFuncAttributeMaxDynamicSharedMemorySize,
                         MMA_SMEM);

    dim3 tc_grid((NN + GBM - 1) / GBM, HH / GBN);
    int splitA_blocks = (NN * HH) / (256 * 4);
    int splitW_blocks = (HH * HH) / 256;

    // CSR build
    k_zero_cnt<<<(NN + 255) / 256, 256>>>();
    k_count<<<(EE + 255) / 256, 256>>>(ei);
    k_scan<<<1, 1024>>>();
    k_dinv<<<(NN + 255) / 256, 256>>>();
    k_fill<<<(EE + 255) / 256, 256>>>(ei);

    // GCN layer 1: x[N,3] -> bufB -> agg -> bufA
    k_lin3<<<NN, 256>>>(x, w1, bufB);
    k_gcn_agg<<<NN, 256>>>(bufB, bufA, b1);

    // GCN layer 2: bufA @ w2 -> bufB -> agg -> bufC
    k_split_a<<<splitA_blocks, 256>>>(bufA, Ah, Al);
    k_split_w<<<splitW_blocks, 256>>>(w2, Wh, Wl);
    k_mma_gemm<<<tc_grid, 256, MMA_SMEM>>>(Ah, Al, Wh, Wl, bufB);
    k_gcn_agg<<<NN, 256>>>(bufB, bufC, b2);

    // GCN layer 3: bufC @ w3 -> bufB -> agg -> bufA
    k_split_a<<<splitA_blocks, 256>>>(bufC, Ah, Al);
    k_split_w<<<splitW_blocks, 256>>>(w3, Wh, Wl);
    k_mma_gemm<<<tc_grid, 256, MMA_SMEM>>>(Ah, Al, Wh, Wl, bufB);
    k_gcn_agg<<<NN, 256>>>(bufB, bufA, b3);

    // GAT layer 1: bufA @ wg1 -> bufB (Hg) ; alpha ; agg -> bufC (relu)
    k_split_a<<<splitA_blocks, 256>>>(bufA, Ah, Al);
    k_split_w<<<splitW_blocks, 256>>>(wg1, Wh, Wl);
    k_mma_gemm<<<tc_grid, 256, MMA_SMEM>>>(Ah, Al, Wh, Wl, bufB);
    k_alpha<<<(NN * NHD * 32 + 255) / 256, 256>>>(bufB, as1, ad1);
    k_gat_agg<<<NN, 256>>>(bufB, bufC, bg1, 1);

    // GAT layer 2: bufC @ wg2 -> bufB ; alpha ; agg -> bufA (no relu)
    k_split_a<<<splitA_blocks, 256>>>(bufC, Ah, Al);
    k_split_w<<<splitW_blocks, 256>>>(wg2, Wh, Wl);
    k_mma_gemm<<<tc_grid, 256, MMA_SMEM>>>(Ah, Al, Wh, Wl, bufB);
    k_alpha<<<(NN * NHD * 32 + 255) / 256, 256>>>(bufB, as2, ad2);
    k_gat_agg<<<NN, 256>>>(bufB, bufA, bg2, 0);

    // pool + MLP
    k_pool<<<NGR * 12, 64>>>(bufA, batc);
    k_mlp1<<<NGR, H2>>>(wc1, bc1);
    k_mlp2<<<NGR, 64>>>(wc2, bc2, out);
}